// round 1
// baseline (speedup 1.0000x reference)
#include <cuda_runtime.h>
#include <cuda_bf16.h>
#include <cstdint>

// Problem constants
#define NUM_CH   544     // 32 batches * 17 keypoints
#define HH       256
#define WW       256
#define MAXP     30
#define STRIDE_  4
#define THRESH   0.1f

// Selection machinery
#define LIST_CAP 9216    // expected survivors ~7300 (density ~1/9 of 65536)
#define CAND_CAP 2048
#define NBINS    256
#define THREADS  512

struct SmemT {
    float score[LIST_CAP];
    int   sidx [LIST_CAP];
    float cs   [CAND_CAP];
    int   ci   [CAND_CAP];
    int   hist [NBINS];
    int   count;
    int   cut;
    int   ncand;
};

__global__ __launch_bounds__(THREADS, 1)
void pose_post_kernel(const float* __restrict__ hm, float* __restrict__ out)
{
    extern __shared__ SmemT sh[];
    SmemT& s = sh[0];

    const int tid = threadIdx.x;
    const int ch  = blockIdx.x;
    const float* __restrict__ chm = hm + (size_t)ch * HH * WW;
    const float NI = __int_as_float(0xff800000);  // -inf

    // ---- init shared ----
    for (int i = tid; i < NBINS; i += THREADS) s.hist[i] = 0;
    if (tid == 0) { s.count = 0; s.ncand = 0; }
    __syncthreads();

    // ---- Phase 1: single-pass NMS scan ----
    // 16 warps: band = wid&7 (32-column stripe), half = wid>>3 (128-row half).
    // NMS trick: keep pixel iff v == max of full 3x3 window (center included),
    // identical to reference's (hmax == heatmaps).
    const int wid  = tid >> 5;
    const int lane = tid & 31;
    const int band = wid & 7;
    const int half = wid >> 3;
    const int col  = band * 32 + lane;
    const int r0   = half * 128;
    const int r1   = r0 + 128;

    float rmA = NI, rmB = NI, vB = NI;   // rowmax[r-2], rowmax[r-1], v[r-1]
    for (int rr = r0 - 1; rr <= r1; ++rr) {
        float v = NI, rm = NI;
        if (rr >= 0 && rr < HH) {
            const int base = rr * WW + col;
            v = __ldg(chm + base);
            float lft = __shfl_up_sync(0xffffffffu, v, 1);
            if (lane == 0)  lft = (col == 0)      ? NI : __ldg(chm + base - 1);
            float rgt = __shfl_down_sync(0xffffffffu, v, 1);
            if (lane == 31) rgt = (col == WW - 1) ? NI : __ldg(chm + base + 1);
            rm = fmaxf(fmaxf(lft, rgt), v);
        }
        const int dr = rr - 1;           // row being decided
        if (dr >= r0 && dr < r1) {       // uniform per warp
            const float win = fmaxf(fmaxf(rmA, rmB), rm);
            const bool keep = (vB > THRESH) && (vB == win);
            const unsigned m = __ballot_sync(0xffffffffu, keep);
            if (m) {
                int base2 = 0;
                const int leader = __ffs(m) - 1;
                if (lane == leader) base2 = atomicAdd(&s.count, __popc(m));
                base2 = __shfl_sync(0xffffffffu, base2, leader);
                if (keep) {
                    const int pos = base2 + __popc(m & ((1u << lane) - 1u));
                    if (pos < LIST_CAP) { s.score[pos] = vB; s.sidx[pos] = dr * WW + col; }
                    int bin = (int)((vB - THRESH) * (256.0f / 0.9f));
                    bin = max(0, min(NBINS - 1, bin));
                    atomicAdd(&s.hist[bin], 1);
                }
            }
        }
        rmA = rmB; rmB = rm; vB = v;
    }
    __syncthreads();

    // ---- Phase 2: histogram cutoff (suffix count >= MAXP) ----
    if (tid == 0) {
        int tot = 0, cb = 0;
        for (int b = NBINS - 1; b >= 0; --b) {
            tot += s.hist[b];
            if (tot >= MAXP) { cb = b; break; }
        }
        s.cut = cb;
    }
    __syncthreads();

    // ---- Phase 3: compact candidates above cutoff bin ----
    const int cnt    = min(s.count, LIST_CAP);
    const int cutbin = s.cut;
    for (int i = tid; i < cnt; i += THREADS) {
        const float sc = s.score[i];
        int bin = (int)((sc - THRESH) * (256.0f / 0.9f));
        bin = max(0, min(NBINS - 1, bin));
        if (bin >= cutbin) {
            const int p = atomicAdd(&s.ncand, 1);
            if (p < CAND_CAP) { s.cs[p] = sc; s.ci[p] = s.sidx[i]; }
        }
    }
    __syncthreads();

    // ---- Phase 4: exact rank (score desc, idx asc tiebreak == lax.top_k) ----
    const int n = min(s.ncand, CAND_CAP);
    for (int i = tid; i < n; i += THREADS) {
        const float sc = s.cs[i];
        const int   id = s.ci[i];
        int rank = 0;
        for (int j = 0; j < n; ++j) {
            const float sj = s.cs[j];
            rank += (sj > sc) || (sj == sc && s.ci[j] < id);
        }
        if (rank < MAXP) {
            const int x  = id & (WW - 1);
            const int y  = id >> 8;
            const int ob = ch * MAXP + rank;
            out[ob * 2]                     = (float)(x * STRIDE_);
            out[ob * 2 + 1]                 = (float)(y * STRIDE_);
            out[NUM_CH * MAXP * 2 + ob]     = sc;      // scores segment
            out[NUM_CH * MAXP * 3 + ob]     = 1.0f;    // valid segment
        }
    }
    // Fallback fill if fewer than MAXP candidates (never triggers on this input,
    // but keeps d_out fully written / deterministic).
    for (int r = n + tid; r < MAXP; r += THREADS) {
        const int ob = ch * MAXP + r;
        out[ob * 2]                 = 0.0f;
        out[ob * 2 + 1]             = 0.0f;
        out[NUM_CH * MAXP * 2 + ob] = NI;
        out[NUM_CH * MAXP * 3 + ob] = 0.0f;
    }
}

extern "C" void kernel_launch(void* const* d_in, const int* in_sizes, int n_in,
                              void* d_out, int out_size)
{
    const float* hm = (const float*)d_in[0];
    float* out = (float*)d_out;
    cudaFuncSetAttribute(pose_post_kernel,
                         cudaFuncAttributeMaxDynamicSharedMemorySize,
                         (int)sizeof(SmemT));
    pose_post_kernel<<<NUM_CH, THREADS, sizeof(SmemT)>>>(hm, out);
}

// round 2
// speedup vs baseline: 1.2706x; 1.2706x over previous
#include <cuda_runtime.h>
#include <cuda_bf16.h>
#include <cstdint>

// Problem constants
#define NUM_CH   544     // 32 batches * 17 keypoints
#define HH       256
#define WW       256
#define MAXP     30
#define STRIDE_  4
#define THRESH   0.1f

// Selection machinery
#define LIST_CAP 8192    // expected survivors ~7282 (1/9 of 65536), sigma~80 -> 11 sigma headroom
#define CAND_CAP 512
#define NBINS    1024
#define THREADS  512
#define FULL     0xffffffffu

struct SmemT {
    float          score[LIST_CAP];   // 32 KB
    unsigned short sidx [LIST_CAP];   // 16 KB (idx in [0,65535] fits exactly)
    int            hist [NBINS];      //  4 KB
    float          cs   [CAND_CAP];   //  2 KB
    unsigned short ci   [CAND_CAP];   //  1 KB
    int            count;
    int            cut;
    int            ncand;
};

__global__ __launch_bounds__(THREADS, 3)
void pose_post_kernel(const float* __restrict__ hm, float* __restrict__ out)
{
    extern __shared__ SmemT sh[];
    SmemT& s = sh[0];

    const int tid = threadIdx.x;
    const int ch  = blockIdx.x;
    const float* __restrict__ chm = hm + (size_t)ch * HH * WW;
    const float NI = __int_as_float(0xff800000);  // -inf

    // ---- init shared ----
    for (int i = tid; i < NBINS; i += THREADS) s.hist[i] = 0;
    if (tid == 0) { s.count = 0; s.ncand = 0; }
    __syncthreads();

    // ---- Phase 1: vectorized single-pass NMS scan ----
    // 16 warps: band = wid&1 (128-col stripe, 32 lanes x float4), strip = wid>>1
    // (32-row slice). Keep pixel iff v == max of FULL 3x3 window (center incl.)
    // and v > THRESH — identical to reference's heat * (hmax == heat) > 0.1.
    const int lane  = tid & 31;
    const int wid   = tid >> 5;
    const int band  = wid & 1;
    const int strip = wid >> 1;
    const int col4  = band * 128 + lane * 4;
    const int r0    = strip * 32;
    const int r1    = r0 + 32;

    float4 rmA = make_float4(NI, NI, NI, NI);  // rowmax[dr-1]
    float4 rmB = rmA;                          // rowmax[dr]
    float4 vB  = rmA;                          // v[dr]  (dr = row being decided)

    // prologue: load rr = r0-1
    float4 v  = make_float4(NI, NI, NI, NI);
    float  hL = NI, hR = NI;
    if (r0 - 1 >= 0) {
        v = *(const float4*)(chm + (r0 - 1) * WW + col4);
        if (lane == 0  && band == 1) hL = __ldg(chm + (r0 - 1) * WW + 127);
        if (lane == 31 && band == 0) hR = __ldg(chm + (r0 - 1) * WW + 128);
    }

    for (int rr = r0 - 1; rr <= r1; ++rr) {
        // prefetch next row (keeps >=2 loads in flight across the iteration)
        float4 vn  = make_float4(NI, NI, NI, NI);
        float  hLn = NI, hRn = NI;
        const int rn = rr + 1;
        if (rn <= r1 && rn < HH) {
            vn = *(const float4*)(chm + rn * WW + col4);
            if (lane == 0  && band == 1) hLn = __ldg(chm + rn * WW + 127);
            if (lane == 31 && band == 0) hRn = __ldg(chm + rn * WW + 128);
        }

        // horizontal 3-max for current row rr
        float lft = __shfl_up_sync(FULL, v.w, 1);
        if (lane == 0)  lft = hL;   // NI at image edge (band 0)
        float rgt = __shfl_down_sync(FULL, v.x, 1);
        if (lane == 31) rgt = hR;   // NI at image edge (band 1)

        float4 rm;
        rm.x = fmaxf(fmaxf(lft, v.x), v.y);
        rm.y = fmaxf(fmaxf(v.x, v.y), v.z);
        rm.z = fmaxf(fmaxf(v.y, v.z), v.w);
        rm.w = fmaxf(fmaxf(v.z, v.w), rgt);

        const int dr = rr - 1;          // row being decided (uniform per warp)
        if (dr >= r0) {
            const bool k0 = (vB.x > THRESH) && (vB.x == fmaxf(fmaxf(rmA.x, rmB.x), rm.x));
            const bool k1 = (vB.y > THRESH) && (vB.y == fmaxf(fmaxf(rmA.y, rmB.y), rm.y));
            const bool k2 = (vB.z > THRESH) && (vB.z == fmaxf(fmaxf(rmA.z, rmB.z), rm.z));
            const bool k3 = (vB.w > THRESH) && (vB.w == fmaxf(fmaxf(rmA.w, rmB.w), rm.w));

            const unsigned m0 = __ballot_sync(FULL, k0);
            const unsigned m1 = __ballot_sync(FULL, k1);
            const unsigned m2 = __ballot_sync(FULL, k2);
            const unsigned m3 = __ballot_sync(FULL, k3);
            const int p0 = __popc(m0), p1 = __popc(m1), p2 = __popc(m2);
            const int tot = p0 + p1 + p2 + __popc(m3);
            if (tot) {
                int base = 0;
                if (lane == 0) base = atomicAdd(&s.count, tot);
                base = __shfl_sync(FULL, base, 0);
                const unsigned lt = (1u << lane) - 1u;
                const int ibase = dr * WW + col4;
                if (k0) { int p = base + __popc(m0 & lt);
                          if (p < LIST_CAP) { s.score[p] = vB.x; s.sidx[p] = (unsigned short)(ibase);     } }
                if (k1) { int p = base + p0 + __popc(m1 & lt);
                          if (p < LIST_CAP) { s.score[p] = vB.y; s.sidx[p] = (unsigned short)(ibase + 1); } }
                if (k2) { int p = base + p0 + p1 + __popc(m2 & lt);
                          if (p < LIST_CAP) { s.score[p] = vB.z; s.sidx[p] = (unsigned short)(ibase + 2); } }
                if (k3) { int p = base + p0 + p1 + p2 + __popc(m3 & lt);
                          if (p < LIST_CAP) { s.score[p] = vB.w; s.sidx[p] = (unsigned short)(ibase + 3); } }
            }
        }
        rmA = rmB; rmB = rm; vB = v;
        v = vn; hL = hLn; hR = hRn;
    }
    __syncthreads();

    // ---- Phase 2: build histogram from survivor list ----
    const int cnt = min(s.count, LIST_CAP);
    for (int i = tid; i < cnt; i += THREADS) {
        const float sc = s.score[i];
        int b = (int)((sc - THRESH) * ((float)NBINS / 0.9f));
        b = max(0, min(NBINS - 1, b));
        atomicAdd(&s.hist[b], 1);
    }
    __syncthreads();

    // ---- Phase 3: cutoff bin (suffix count >= MAXP; expected break in ~1 iter) ----
    if (tid == 0) {
        int tot = 0, cb = 0;
        for (int b = NBINS - 1; b >= 0; --b) {
            tot += s.hist[b];
            if (tot >= MAXP) { cb = b; break; }
        }
        s.cut = cb;
    }
    __syncthreads();

    // ---- Phase 4: compact candidates above cutoff bin ----
    const int cutbin = s.cut;
    for (int i = tid; i < cnt; i += THREADS) {
        const float sc = s.score[i];
        int b = (int)((sc - THRESH) * ((float)NBINS / 0.9f));
        b = max(0, min(NBINS - 1, b));
        if (b >= cutbin) {
            const int p = atomicAdd(&s.ncand, 1);
            if (p < CAND_CAP) { s.cs[p] = sc; s.ci[p] = s.sidx[i]; }
        }
    }
    __syncthreads();

    // ---- Phase 5: exact rank (score desc, idx asc tiebreak == lax.top_k) ----
    const int n = min(s.ncand, CAND_CAP);
    for (int i = tid; i < n; i += THREADS) {
        const float sc = s.cs[i];
        const int   id = s.ci[i];
        int rank = 0;
        for (int j = 0; j < n; ++j) {
            const float sj = s.cs[j];
            rank += (sj > sc) || (sj == sc && s.ci[j] < id);
        }
        if (rank < MAXP) {
            const int x  = id & (WW - 1);
            const int y  = id >> 8;
            const int ob = ch * MAXP + rank;
            out[ob * 2]                     = (float)(x * STRIDE_);
            out[ob * 2 + 1]                 = (float)(y * STRIDE_);
            out[NUM_CH * MAXP * 2 + ob]     = sc;      // scores segment
            out[NUM_CH * MAXP * 3 + ob]     = 1.0f;    // valid segment
        }
    }
    // Fallback fill if fewer than MAXP candidates (keeps d_out deterministic).
    for (int r = n + tid; r < MAXP; r += THREADS) {
        const int ob = ch * MAXP + r;
        out[ob * 2]                 = 0.0f;
        out[ob * 2 + 1]             = 0.0f;
        out[NUM_CH * MAXP * 2 + ob] = NI;
        out[NUM_CH * MAXP * 3 + ob] = 0.0f;
    }
}

extern "C" void kernel_launch(void* const* d_in, const int* in_sizes, int n_in,
                              void* d_out, int out_size)
{
    const float* hm = (const float*)d_in[0];
    float* out = (float*)d_out;
    cudaFuncSetAttribute(pose_post_kernel,
                         cudaFuncAttributeMaxDynamicSharedMemorySize,
                         (int)sizeof(SmemT));
    pose_post_kernel<<<NUM_CH, THREADS, sizeof(SmemT)>>>(hm, out);
}

// round 4
// speedup vs baseline: 4.8582x; 3.8234x over previous
#include <cuda_runtime.h>
#include <cuda_bf16.h>
#include <cstdint>

#define NUM_CH   544     // 32 batches * 17 keypoints
#define HH       256
#define WW       256
#define MAXP     30
#define STRIDE_  4
#define THRESH   0.1f
#define CUT      0.9985f // expected ~98 survivors/channel (>> 30); fallback if fewer
#define CAP      512
#define THREADS  512
#define RPW      16      // rows decided per warp (16 warps x 16 rows = 256)
#define FULL     0xffffffffu

// Fallback scratch (exact path, never triggered on this input). Static device
// arrays are the sanctioned no-alloc workaround.
__device__ float g_fb_score[(size_t)NUM_CH * 65536];
__device__ int   g_fb_idx  [(size_t)NUM_CH * 65536];

struct Sm {
    float sc[CAP];
    int   si[CAP];
    int   count;
};

// One full NMS scan of a 256x256 channel. Keep pixel iff v > cut AND
// v == max of its full 3x3 window (identical to reference hmax==heat gating).
// Appends (score, flat_idx) through generic pointers (smem or gmem).
static __device__ __noinline__ void scan_pass(const float* __restrict__ chm,
                                              float cut, float* ds, int* di,
                                              int cap, int* cnt)
{
    const int lane = threadIdx.x & 31;
    const int wid  = threadIdx.x >> 5;
    const int r0   = wid * RPW;
    const int c0   = lane * 8;
    const float NI = __int_as_float(0xff800000);

    float P0[8], P1[8], P2[8], vD[8], rmA[8], rmB[8];
    float lmD = NI;

    // row loader: 8 px/lane as 2x float4; out-of-range rows = -inf
    auto LD = [&](int row, float* dst) {
        if ((unsigned)row < HH) {
            const float4 lo = *(const float4*)(chm + row * WW + c0);
            const float4 hi = *(const float4*)(chm + row * WW + c0 + 4);
            dst[0]=lo.x; dst[1]=lo.y; dst[2]=lo.z; dst[3]=lo.w;
            dst[4]=hi.x; dst[5]=hi.y; dst[6]=hi.z; dst[7]=hi.w;
        } else {
            #pragma unroll
            for (int i = 0; i < 8; ++i) dst[i] = NI;
        }
    };

    LD(r0 - 1, P0);
    LD(r0,     P1);
    #pragma unroll
    for (int i = 0; i < 8; ++i) { rmA[i] = NI; rmB[i] = NI; vD[i] = NI; }

    #pragma unroll
    for (int t = 0; t < RPW + 2; ++t) {
        const int rr = r0 - 1 + t;       // row whose rowmax we compute (in P0)
        // prefetch 2 rows ahead; rows beyond the strip/image resolve to -inf
        // inside LD's bounds check (only rows < r0+RPW+2 are ever requested,
        // and the t>RPW-1 requests land out of [0,HH) or are unused -inf fills)
        if (t <= RPW - 1) {
            LD(rr + 2, P2);
        } else {
            #pragma unroll
            for (int i = 0; i < 8; ++i) P2[i] = NI;
        }

        // horizontal 3-max of row rr
        float lft = __shfl_up_sync(FULL, P0[7], 1);
        if (lane == 0)  lft = NI;
        float rgt = __shfl_down_sync(FULL, P0[0], 1);
        if (lane == 31) rgt = NI;

        float m[7];
        #pragma unroll
        for (int i = 0; i < 7; ++i) m[i] = fmaxf(P0[i], P0[i + 1]);
        float rmC[8];
        rmC[0] = fmaxf(lft, m[0]);
        #pragma unroll
        for (int i = 1; i < 7; ++i) rmC[i] = fmaxf(m[i - 1], P0[i + 1]);
        rmC[7] = fmaxf(m[6], rgt);
        const float lm = fmaxf(fmaxf(m[0], m[2]), fmaxf(m[4], m[6])); // lane max of raw row

        if (t >= 2) {                    // decide row dr = rr-1 (uniform branch)
            const int dr = rr - 1;
            if (__any_sync(FULL, lmD > cut)) {       // rare with high cut
                #pragma unroll
                for (int i = 0; i < 8; ++i) {
                    const float w = fmaxf(fmaxf(rmA[i], rmB[i]), rmC[i]);
                    if (vD[i] > cut && vD[i] == w) {
                        const int p = atomicAdd(cnt, 1);
                        if (p < cap) { ds[p] = vD[i]; di[p] = dr * WW + c0 + i; }
                    }
                }
            }
        }
        // rotate pipeline state
        #pragma unroll
        for (int i = 0; i < 8; ++i) {
            rmA[i] = rmB[i]; rmB[i] = rmC[i];
            vD[i]  = P0[i];  P0[i]  = P1[i]; P1[i] = P2[i];
        }
        lmD = lm;
    }
}

__global__ __launch_bounds__(THREADS, 2)
void pose_post_kernel(const float* __restrict__ hm, float* __restrict__ out)
{
    __shared__ Sm s;
    const int tid = threadIdx.x;
    const int ch  = blockIdx.x;
    const float* __restrict__ chm = hm + (size_t)ch * HH * WW;
    const float NI = __int_as_float(0xff800000);

    if (tid == 0) s.count = 0;
    __syncthreads();

    scan_pass(chm, CUT, s.sc, s.si, CAP, &s.count);
    __syncthreads();

    int n = min(s.count, CAP);
    const float* rs = s.sc;
    const int*   ri = s.si;

    if (s.count < MAXP || s.count > CAP) {
        // Exact fallback: full-threshold scan into global scratch.
        __syncthreads();
        if (tid == 0) s.count = 0;
        __syncthreads();
        float* gs = g_fb_score + (size_t)ch * 65536;
        int*   gi = g_fb_idx   + (size_t)ch * 65536;
        scan_pass(chm, THRESH, gs, gi, 65536, &s.count);
        __syncthreads();
        n = min(s.count, 65536);
        rs = gs; ri = gi;
    }

    // Exact rank (score desc, idx asc tiebreak == lax.top_k order).
    for (int i = tid; i < n; i += THREADS) {
        const float sc = rs[i];
        const int   id = ri[i];
        int rank = 0;
        for (int j = 0; j < n; ++j) {
            const float sj = rs[j];
            rank += (sj > sc) || (sj == sc && ri[j] < id);
        }
        if (rank < MAXP) {
            const int x  = id & (WW - 1);
            const int y  = id >> 8;
            const int ob = ch * MAXP + rank;
            out[ob * 2]                 = (float)(x * STRIDE_);
            out[ob * 2 + 1]             = (float)(y * STRIDE_);
            out[NUM_CH * MAXP * 2 + ob] = sc;     // scores segment
            out[NUM_CH * MAXP * 3 + ob] = 1.0f;   // valid segment
        }
    }
    // Padding (n < MAXP never happens on this input; keeps d_out fully written).
    for (int r = n + tid; r < MAXP; r += THREADS) {
        const int ob = ch * MAXP + r;
        out[ob * 2]                 = 0.0f;
        out[ob * 2 + 1]             = 0.0f;
        out[NUM_CH * MAXP * 2 + ob] = NI;
        out[NUM_CH * MAXP * 3 + ob] = 0.0f;
    }
}

extern "C" void kernel_launch(void* const* d_in, const int* in_sizes, int n_in,
                              void* d_out, int out_size)
{
    const float* hm = (const float*)d_in[0];
    float* out = (float*)d_out;
    pose_post_kernel<<<NUM_CH, THREADS>>>(hm, out);
}

// round 6
// speedup vs baseline: 5.7953x; 1.1929x over previous
#include <cuda_runtime.h>
#include <cuda_bf16.h>
#include <cstdint>

#define NUM_CH   544     // 32 batches * 17 keypoints
#define HH       256
#define WW       256
#define MAXP     30
#define STRIDE_  4
#define THRESH   0.1f
#define CUT      0.9985f // ~98 threshold-only candidates/channel expected
#define CAP      512
#define THREADS  512
#define RPW      16
#define FULL     0xffffffffu

// Fallback scratch (exact path, never triggered on this input).
__device__ float g_fb_score[(size_t)NUM_CH * 65536];
__device__ int   g_fb_idx  [(size_t)NUM_CH * 65536];

struct Sm {
    float cs[CAP]; int ci[CAP];   // threshold-only candidates
    float ps[CAP]; int pi[CAP];   // verified peaks
    int ccount;
    int pcount;
};

// Fallback: full NMS scan with register pipeline (proven in R4). Keep pixel iff
// v > cut AND v == max of full 3x3 window. Never runs on this input; spills OK.
static __device__ __noinline__ void scan_pass(const float* __restrict__ chm,
                                              float cut, float* ds, int* di,
                                              int cap, int* cnt)
{
    const int lane = threadIdx.x & 31;
    const int wid  = threadIdx.x >> 5;
    const int r0   = wid * RPW;
    const int c0   = lane * 8;
    const float NI = __int_as_float(0xff800000);

    float P0[8], P1[8], P2[8], vD[8], rmA[8], rmB[8];

    auto LD = [&](int row, float* dst) {
        if ((unsigned)row < HH) {
            const float4 lo = *(const float4*)(chm + row * WW + c0);
            const float4 hi = *(const float4*)(chm + row * WW + c0 + 4);
            dst[0]=lo.x; dst[1]=lo.y; dst[2]=lo.z; dst[3]=lo.w;
            dst[4]=hi.x; dst[5]=hi.y; dst[6]=hi.z; dst[7]=hi.w;
        } else {
            for (int i = 0; i < 8; ++i) dst[i] = NI;
        }
    };

    LD(r0 - 1, P0);
    LD(r0,     P1);
    for (int i = 0; i < 8; ++i) { rmA[i] = NI; rmB[i] = NI; vD[i] = NI; }

    for (int t = 0; t < RPW + 2; ++t) {
        const int rr = r0 - 1 + t;
        if (t <= RPW - 1) {
            LD(rr + 2, P2);
        } else {
            for (int i = 0; i < 8; ++i) P2[i] = NI;
        }
        float lft = __shfl_up_sync(FULL, P0[7], 1);
        if (lane == 0)  lft = NI;
        float rgt = __shfl_down_sync(FULL, P0[0], 1);
        if (lane == 31) rgt = NI;

        float m[7];
        for (int i = 0; i < 7; ++i) m[i] = fmaxf(P0[i], P0[i + 1]);
        float rmC[8];
        rmC[0] = fmaxf(lft, m[0]);
        for (int i = 1; i < 7; ++i) rmC[i] = fmaxf(m[i - 1], P0[i + 1]);
        rmC[7] = fmaxf(m[6], rgt);

        if (t >= 2) {
            const int dr = rr - 1;
            for (int i = 0; i < 8; ++i) {
                const float w = fmaxf(fmaxf(rmA[i], rmB[i]), rmC[i]);
                if (vD[i] > cut && vD[i] == w) {
                    const int p = atomicAdd(cnt, 1);
                    if (p < cap) { ds[p] = vD[i]; di[p] = dr * WW + c0 + i; }
                }
            }
        }
        for (int i = 0; i < 8; ++i) {
            rmA[i] = rmB[i]; rmB[i] = rmC[i];
            vD[i]  = P0[i];  P0[i]  = P1[i]; P1[i] = P2[i];
        }
    }
}

__global__ __launch_bounds__(THREADS, 4)
void pose_post_kernel(const float* __restrict__ hm, float* __restrict__ out)
{
    __shared__ Sm s;
    const int tid = threadIdx.x;
    const int ch  = blockIdx.x;
    const float* __restrict__ chm = hm + (size_t)ch * HH * WW;
    const float NI = __int_as_float(0xff800000);

    if (tid == 0) { s.ccount = 0; s.pcount = 0; }
    __syncthreads();

    // ---- Phase A: pure streaming threshold scan (the only full-data pass) ----
    // thread t reads float4 index i*512 + t : fully coalesced, 32 independent
    // LDG.128 per thread, minimal registers -> max MLP at 4 CTAs/SM.
    const float4* __restrict__ chm4 = (const float4*)chm;
    #pragma unroll 4
    for (int i = 0; i < 32; ++i) {
        const int q = i * THREADS + tid;
        const float4 v = chm4[q];
        const float mx = fmaxf(fmaxf(v.x, v.y), fmaxf(v.z, v.w));
        if (mx > CUT) {                       // ~0.6% of float4s
            const int fb = q * 4;
            if (v.x > CUT) { int p = atomicAdd(&s.ccount, 1); if (p < CAP) { s.cs[p] = v.x; s.ci[p] = fb;     } }
            if (v.y > CUT) { int p = atomicAdd(&s.ccount, 1); if (p < CAP) { s.cs[p] = v.y; s.ci[p] = fb + 1; } }
            if (v.z > CUT) { int p = atomicAdd(&s.ccount, 1); if (p < CAP) { s.cs[p] = v.z; s.ci[p] = fb + 2; } }
            if (v.w > CUT) { int p = atomicAdd(&s.ccount, 1); if (p < CAP) { s.cs[p] = v.w; s.ci[p] = fb + 3; } }
        }
    }
    __syncthreads();

    const int nc = s.ccount;
    const bool ok = (nc <= CAP);

    // ---- Phase B: 3x3 window check on the ~98 candidates (L2-resident reads) ----
    if (ok) {
        for (int i = tid; i < nc; i += THREADS) {
            const float v  = s.cs[i];
            const int   id = s.ci[i];
            const int x = id & (WW - 1);
            const int y = id >> 8;
            const float* rp = chm + id;
            bool peak = true;
            if (x > 0      && __ldg(rp - 1)       > v) peak = false;
            if (x < WW - 1 && __ldg(rp + 1)       > v) peak = false;
            if (y > 0) {
                if (             __ldg(rp - WW)     > v) peak = false;
                if (x > 0      && __ldg(rp - WW - 1) > v) peak = false;
                if (x < WW - 1 && __ldg(rp - WW + 1) > v) peak = false;
            }
            if (y < HH - 1) {
                if (             __ldg(rp + WW)     > v) peak = false;
                if (x > 0      && __ldg(rp + WW - 1) > v) peak = false;
                if (x < WW - 1 && __ldg(rp + WW + 1) > v) peak = false;
            }
            if (peak) {
                const int p = atomicAdd(&s.pcount, 1);  // p < nc <= CAP
                s.ps[p] = v; s.pi[p] = id;
            }
        }
        __syncthreads();
    }

    int n = ok ? s.pcount : 0;
    const float* rs = s.ps;
    const int*   ri = s.pi;

    if (!ok || n < MAXP) {
        // Exact fallback: full NMS scan at THRESH into global scratch.
        __syncthreads();
        if (tid == 0) s.ccount = 0;
        __syncthreads();
        float* gs = g_fb_score + (size_t)ch * 65536;
        int*   gi = g_fb_idx   + (size_t)ch * 65536;
        scan_pass(chm, THRESH, gs, gi, 65536, &s.ccount);
        __syncthreads();
        n = min(s.ccount, 65536);
        rs = gs; ri = gi;
    }

    // ---- Exact rank (score desc, idx asc tiebreak == lax.top_k order) ----
    for (int i = tid; i < n; i += THREADS) {
        const float sc = rs[i];
        const int   id = ri[i];
        int rank = 0;
        for (int j = 0; j < n; ++j) {
            const float sj = rs[j];
            rank += (sj > sc) || (sj == sc && ri[j] < id);
        }
        if (rank < MAXP) {
            const int x  = id & (WW - 1);
            const int y  = id >> 8;
            const int ob = ch * MAXP + rank;
            out[ob * 2]                 = (float)(x * STRIDE_);
            out[ob * 2 + 1]             = (float)(y * STRIDE_);
            out[NUM_CH * MAXP * 2 + ob] = sc;     // scores segment
            out[NUM_CH * MAXP * 3 + ob] = 1.0f;   // valid segment
        }
    }
    // Padding (never needed on this input; keeps d_out fully written).
    for (int r = n + tid; r < MAXP; r += THREADS) {
        const int ob = ch * MAXP + r;
        out[ob * 2]                 = 0.0f;
        out[ob * 2 + 1]             = 0.0f;
        out[NUM_CH * MAXP * 2 + ob] = NI;
        out[NUM_CH * MAXP * 3 + ob] = 0.0f;
    }
}

extern "C" void kernel_launch(void* const* d_in, const int* in_sizes, int n_in,
                              void* d_out, int out_size)
{
    const float* hm = (const float*)d_in[0];
    float* out = (float*)d_out;
    pose_post_kernel<<<NUM_CH, THREADS>>>(hm, out);
}